// round 12
// baseline (speedup 1.0000x reference)
#include <cuda_runtime.h>

// CornerActivationB: ARITY=2, GROUPS=512, OUT_DIM=16, BATCH=8192
//
// out[b,g,:] = bilinear interp of 4 corner param vectors with
//   a = (clip(x0,-1,1)+1)/2, bb = (clip(x1,-1,1)+1)/2
//
// R3 change: params register-resident per thread (fixed (g,d4)), loop over a
// 64-row batch tile. Cuts L1 wavefronts/warp/row from ~22 to ~5 -> DRAM-bound.

#define GROUPS   512
#define OUT_DIM  16
#define G_TILE   64     // groups per block  (256 threads / 4 d4-lanes)
#define B_TILE   64     // batch rows per block

__global__ __launch_bounds__(256)
void corner_act_kernel(const float* __restrict__ X,
                       const float* __restrict__ P,
                       float* __restrict__ out,
                       int batch)
{
    const unsigned tid = threadIdx.x;
    const unsigned d4  = tid & 3u;                       // which float4 of the 16 dims
    const unsigned g   = blockIdx.x * G_TILE + (tid >> 2);

    // ---- load this thread's 4 corner param float4s ONCE (L1 hit, amortized) ----
    const float4* pg = reinterpret_cast<const float4*>(P + (size_t)g * (4 * OUT_DIM)) + d4;
    const float4 p0 = __ldg(pg + 0 * (OUT_DIM / 4));
    const float4 p1 = __ldg(pg + 1 * (OUT_DIM / 4));
    const float4 p2 = __ldg(pg + 2 * (OUT_DIM / 4));
    const float4 p3 = __ldg(pg + 3 * (OUT_DIM / 4));

    const unsigned b0 = blockIdx.y * B_TILE;

    // X: [batch, GROUPS*2]; the (x0,x1) pair for group g is one aligned float2.
    // Lanes sharing g (4 d4 lanes) broadcast the same 8B load.
    const float2* Xg = reinterpret_cast<const float2*>(X) + g;   // row stride = GROUPS float2
    float* obase = out + (size_t)g * OUT_DIM + d4 * 4u;

    #pragma unroll 8
    for (int i = 0; i < B_TILE; ++i) {
        const unsigned b = b0 + i;
        const float2 x = __ldg(Xg + (size_t)b * GROUPS);

        const float a  = 0.5f * (fminf(fmaxf(x.x, -1.0f), 1.0f) + 1.0f);
        const float bb = 0.5f * (fminf(fmaxf(x.y, -1.0f), 1.0f) + 1.0f);
        const float ia = 1.0f - a;
        const float ib = 1.0f - bb;

        const float w00 = ia * ib;
        const float w01 = ia * bb;
        const float w10 = a  * ib;
        const float w11 = a  * bb;

        float4 r;
        r.x = w00 * p0.x + w01 * p1.x + w10 * p2.x + w11 * p3.x;
        r.y = w00 * p0.y + w01 * p1.y + w10 * p2.y + w11 * p3.y;
        r.z = w00 * p0.z + w01 * p1.z + w10 * p2.z + w11 * p3.z;
        r.w = w00 * p0.w + w01 * p1.w + w10 * p2.w + w11 * p3.w;

        *reinterpret_cast<float4*>(obase + (size_t)b * (GROUPS * OUT_DIM)) = r;
    }
}

extern "C" void kernel_launch(void* const* d_in, const int* in_sizes, int n_in,
                              void* d_out, int out_size)
{
    const float* X = (const float*)d_in[0];   // [BATCH, GROUPS*2] fp32
    const float* P = (const float*)d_in[1];   // [GROUPS, 4, OUT_DIM] fp32
    float* out = (float*)d_out;               // [BATCH, GROUPS*OUT_DIM] fp32

    int batch = in_sizes[0] / (GROUPS * 2);   // 8192

    dim3 grid(GROUPS / G_TILE, (batch + B_TILE - 1) / B_TILE);  // 8 x 128
    corner_act_kernel<<<grid, 256>>>(X, P, out, batch);
}

// round 13
// speedup vs baseline: 1.0255x; 1.0255x over previous
#include <cuda_runtime.h>

// CornerActivationB: ARITY=2, GROUPS=512, OUT_DIM=16, BATCH=8192
//
// out[b,g,:] = bilinear interp of 4 corner param vectors with
//   a = (clip(x0,-1,1)+1)/2, bb = (clip(x1,-1,1)+1)/2
//
// R3 change: params register-resident per thread (fixed (g,d4)), loop over a
// 64-row batch tile. Cuts L1 wavefronts/warp/row from ~22 to ~5 -> DRAM-bound.

#define GROUPS   512
#define OUT_DIM  16
#define G_TILE   64     // groups per block  (256 threads / 4 d4-lanes)
#define B_TILE   64     // batch rows per block

__global__ __launch_bounds__(256)
void corner_act_kernel(const float* __restrict__ X,
                       const float* __restrict__ P,
                       float* __restrict__ out,
                       int batch)
{
    const unsigned tid = threadIdx.x;
    const unsigned d4  = tid & 3u;                       // which float4 of the 16 dims
    const unsigned g   = blockIdx.x * G_TILE + (tid >> 2);

    // ---- load this thread's 4 corner param float4s ONCE (L1 hit, amortized) ----
    const float4* pg = reinterpret_cast<const float4*>(P + (size_t)g * (4 * OUT_DIM)) + d4;
    const float4 p0 = __ldg(pg + 0 * (OUT_DIM / 4));
    const float4 p1 = __ldg(pg + 1 * (OUT_DIM / 4));
    const float4 p2 = __ldg(pg + 2 * (OUT_DIM / 4));
    const float4 p3 = __ldg(pg + 3 * (OUT_DIM / 4));

    const unsigned b0 = blockIdx.y * B_TILE;

    // X: [batch, GROUPS*2]; the (x0,x1) pair for group g is one aligned float2.
    // Lanes sharing g (4 d4 lanes) broadcast the same 8B load.
    const float2* Xg = reinterpret_cast<const float2*>(X) + g;   // row stride = GROUPS float2
    float* obase = out + (size_t)g * OUT_DIM + d4 * 4u;

    #pragma unroll 8
    for (int i = 0; i < B_TILE; ++i) {
        const unsigned b = b0 + i;
        const float2 x = __ldg(Xg + (size_t)b * GROUPS);

        const float a  = 0.5f * (fminf(fmaxf(x.x, -1.0f), 1.0f) + 1.0f);
        const float bb = 0.5f * (fminf(fmaxf(x.y, -1.0f), 1.0f) + 1.0f);
        const float ia = 1.0f - a;
        const float ib = 1.0f - bb;

        const float w00 = ia * ib;
        const float w01 = ia * bb;
        const float w10 = a  * ib;
        const float w11 = a  * bb;

        float4 r;
        r.x = w00 * p0.x + w01 * p1.x + w10 * p2.x + w11 * p3.x;
        r.y = w00 * p0.y + w01 * p1.y + w10 * p2.y + w11 * p3.y;
        r.z = w00 * p0.z + w01 * p1.z + w10 * p2.z + w11 * p3.z;
        r.w = w00 * p0.w + w01 * p1.w + w10 * p2.w + w11 * p3.w;

        *reinterpret_cast<float4*>(obase + (size_t)b * (GROUPS * OUT_DIM)) = r;
    }
}

extern "C" void kernel_launch(void* const* d_in, const int* in_sizes, int n_in,
                              void* d_out, int out_size)
{
    const float* X = (const float*)d_in[0];   // [BATCH, GROUPS*2] fp32
    const float* P = (const float*)d_in[1];   // [GROUPS, 4, OUT_DIM] fp32
    float* out = (float*)d_out;               // [BATCH, GROUPS*OUT_DIM] fp32

    int batch = in_sizes[0] / (GROUPS * 2);   // 8192

    dim3 grid(GROUPS / G_TILE, (batch + B_TILE - 1) / B_TILE);  // 8 x 128
    corner_act_kernel<<<grid, 256>>>(X, P, out, batch);
}

// round 14
// speedup vs baseline: 1.0956x; 1.0684x over previous
#include <cuda_runtime.h>

// CornerActivationB: ARITY=2, GROUPS=512, OUT_DIM=16, BATCH=8192
//
// out[b,g,:] = bilinear interp of 4 corner param vectors with
//   a = (clip(x0,-1,1)+1)/2, bb = (clip(x1,-1,1)+1)/2
//
// R3 change: params register-resident per thread (fixed (g,d4)), loop over a
// 64-row batch tile. Cuts L1 wavefronts/warp/row from ~22 to ~5 -> DRAM-bound.

#define GROUPS   512
#define OUT_DIM  16
#define G_TILE   64     // groups per block  (256 threads / 4 d4-lanes)
#define B_TILE   64     // batch rows per block

__global__ __launch_bounds__(256)
void corner_act_kernel(const float* __restrict__ X,
                       const float* __restrict__ P,
                       float* __restrict__ out,
                       int batch)
{
    const unsigned tid = threadIdx.x;
    const unsigned d4  = tid & 3u;                       // which float4 of the 16 dims
    const unsigned g   = blockIdx.x * G_TILE + (tid >> 2);

    // ---- load this thread's 4 corner param float4s ONCE (L1 hit, amortized) ----
    const float4* pg = reinterpret_cast<const float4*>(P + (size_t)g * (4 * OUT_DIM)) + d4;
    const float4 p0 = __ldg(pg + 0 * (OUT_DIM / 4));
    const float4 p1 = __ldg(pg + 1 * (OUT_DIM / 4));
    const float4 p2 = __ldg(pg + 2 * (OUT_DIM / 4));
    const float4 p3 = __ldg(pg + 3 * (OUT_DIM / 4));

    const unsigned b0 = blockIdx.y * B_TILE;

    // X: [batch, GROUPS*2]; the (x0,x1) pair for group g is one aligned float2.
    // Lanes sharing g (4 d4 lanes) broadcast the same 8B load.
    const float2* Xg = reinterpret_cast<const float2*>(X) + g;   // row stride = GROUPS float2
    float* obase = out + (size_t)g * OUT_DIM + d4 * 4u;

    #pragma unroll 8
    for (int i = 0; i < B_TILE; ++i) {
        const unsigned b = b0 + i;
        const float2 x = __ldg(Xg + (size_t)b * GROUPS);

        const float a  = 0.5f * (fminf(fmaxf(x.x, -1.0f), 1.0f) + 1.0f);
        const float bb = 0.5f * (fminf(fmaxf(x.y, -1.0f), 1.0f) + 1.0f);
        const float ia = 1.0f - a;
        const float ib = 1.0f - bb;

        const float w00 = ia * ib;
        const float w01 = ia * bb;
        const float w10 = a  * ib;
        const float w11 = a  * bb;

        float4 r;
        r.x = w00 * p0.x + w01 * p1.x + w10 * p2.x + w11 * p3.x;
        r.y = w00 * p0.y + w01 * p1.y + w10 * p2.y + w11 * p3.y;
        r.z = w00 * p0.z + w01 * p1.z + w10 * p2.z + w11 * p3.z;
        r.w = w00 * p0.w + w01 * p1.w + w10 * p2.w + w11 * p3.w;

        *reinterpret_cast<float4*>(obase + (size_t)b * (GROUPS * OUT_DIM)) = r;
    }
}

extern "C" void kernel_launch(void* const* d_in, const int* in_sizes, int n_in,
                              void* d_out, int out_size)
{
    const float* X = (const float*)d_in[0];   // [BATCH, GROUPS*2] fp32
    const float* P = (const float*)d_in[1];   // [GROUPS, 4, OUT_DIM] fp32
    float* out = (float*)d_out;               // [BATCH, GROUPS*OUT_DIM] fp32

    int batch = in_sizes[0] / (GROUPS * 2);   // 8192

    dim3 grid(GROUPS / G_TILE, (batch + B_TILE - 1) / B_TILE);  // 8 x 128
    corner_act_kernel<<<grid, 256>>>(X, P, out, batch);
}